// round 1
// baseline (speedup 1.0000x reference)
#include <cuda_runtime.h>

#define CDIM 768
#define C4   192          // CDIM/4
#define NTHREADS 256
#define ROWS_PER_WARP 4
#define ROWS_PER_BLOCK 32 // 8 warps * 4 rows
#define QOFF 4096         // scratch stride (max B supported = 4096)

// scratch for quadratic forms: [0,B) = text quad (a'), [QOFF, QOFF+B) = graph quad (c')
__device__ float g_quad[2 * QOFF];

// user_index may be stored int64 (as declared) or int32 (JAX default x64-off).
// Heuristic: read element B/2-1 as int64; it is a valid row index only in the
// 64-bit layout (in the 32-bit layout it packs two indices -> huge value).
__device__ __forceinline__ int detect_is64(const void* uptr, int B, long long nrows) {
    if (B < 2) return 1;
    long long v = ((const long long*)uptr)[B / 2 - 1];
    return (v >= 0 && v < nrows) ? 1 : 0;
}

__device__ __forceinline__ long long load_idx(const void* uptr, int i, int is64) {
    if (is64) return ((const long long*)uptr)[i];
    return (long long)((const int*)uptr)[i];
}

// ---------------------------------------------------------------------------
// Kernel 1 (fused): blocks [0, nCompute) compute quadratic forms x^T W^T x
// into g_quad; blocks [nCompute, gridDim) bulk-copy text -> outT and
// all_user_feature -> outU with streaming loads/stores. Compute issue time
// (~140us) hides under the DRAM-bound copy (~940us).
// ---------------------------------------------------------------------------
__global__ void __launch_bounds__(NTHREADS)
fused_copy_quad(const float* __restrict__ text,
                const float* __restrict__ user,
                const void*  __restrict__ uidx,
                const float* __restrict__ Wt,
                const float* __restrict__ Wg,
                float* __restrict__ outT,
                float* __restrict__ outU,
                int B, long long SC,
                long long text_n, long long user_n,
                long long user_rows,
                int nQ, int nCompute, int nCopyBlocks)
{
    const int bid = blockIdx.x;

    if (bid < nCompute) {
        // ---------------- quadratic-form blocks ----------------
        const int isGraph = (bid >= nQ) ? 1 : 0;
        const int qb = isGraph ? (bid - nQ) : bid;
        const float* __restrict__ W = isGraph ? Wg : Wt;
        const int warp = threadIdx.x >> 5;
        const int lane = threadIdx.x & 31;
        const int row0 = qb * ROWS_PER_BLOCK + warp * ROWS_PER_WARP;
        const int is64 = detect_is64(uidx, B, user_rows);

        // resident x rows: 4 rows x 24 floats/lane (96 regs)
        float4 xr[ROWS_PER_WARP][6];
        #pragma unroll
        for (int r = 0; r < ROWS_PER_WARP; r++) {
            int row = row0 + r;
            if (row >= B) row = B - 1;  // clamp; store is guarded below
            const float4* src;
            if (isGraph) {
                long long u = load_idx(uidx, row, is64);
                src = (const float4*)(user + (size_t)u * CDIM);
            } else {
                src = (const float4*)(text + (size_t)row * SC);
            }
            #pragma unroll
            for (int i = 0; i < 6; i++) xr[r][i] = src[lane + 32 * i];
        }

        float acc[ROWS_PER_WARP] = {0.f, 0.f, 0.f, 0.f};

        #pragma unroll
        for (int ij = 0; ij < 6; ij++) {
            for (int jl = 0; jl < 32; jl++) {
                // broadcast x[r][4*j4 .. 4*j4+3] where j4 = ij*32 + jl
                float4 xb[ROWS_PER_WARP];
                #pragma unroll
                for (int r = 0; r < ROWS_PER_WARP; r++) {
                    xb[r].x = __shfl_sync(0xffffffffu, xr[r][ij].x, jl);
                    xb[r].y = __shfl_sync(0xffffffffu, xr[r][ij].y, jl);
                    xb[r].z = __shfl_sync(0xffffffffu, xr[r][ij].z, jl);
                    xb[r].w = __shfl_sync(0xffffffffu, xr[r][ij].w, jl);
                }
                const int j4 = ij * 32 + jl;
                #pragma unroll
                for (int c = 0; c < 4; c++) {
                    const float4* __restrict__ Wrow =
                        (const float4*)(W + (size_t)(4 * j4 + c) * CDIM);
                    float p[ROWS_PER_WARP] = {0.f, 0.f, 0.f, 0.f};
                    #pragma unroll
                    for (int i = 0; i < 6; i++) {
                        float4 w = Wrow[lane + 32 * i];
                        #pragma unroll
                        for (int r = 0; r < ROWS_PER_WARP; r++) {
                            p[r] += w.x * xr[r][i].x + w.y * xr[r][i].y
                                  + w.z * xr[r][i].z + w.w * xr[r][i].w;
                        }
                    }
                    #pragma unroll
                    for (int r = 0; r < ROWS_PER_WARP; r++) {
                        float xc = (c == 0) ? xb[r].x : (c == 1) ? xb[r].y
                                 : (c == 2) ? xb[r].z : xb[r].w;
                        acc[r] += xc * p[r];
                    }
                }
            }
        }

        #pragma unroll
        for (int r = 0; r < ROWS_PER_WARP; r++) {
            float v = acc[r];
            v += __shfl_xor_sync(0xffffffffu, v, 16);
            v += __shfl_xor_sync(0xffffffffu, v, 8);
            v += __shfl_xor_sync(0xffffffffu, v, 4);
            v += __shfl_xor_sync(0xffffffffu, v, 2);
            v += __shfl_xor_sync(0xffffffffu, v, 1);
            int row = row0 + r;
            if (lane == 0 && row < B) g_quad[isGraph * QOFF + row] = v;
        }
    } else {
        // ---------------- streaming copy blocks ----------------
        const size_t t4 = (size_t)text_n >> 2;
        const size_t u4 = (size_t)user_n >> 2;
        const float4* __restrict__ tin  = (const float4*)text;
        const float4* __restrict__ uin  = (const float4*)user;
        float4* __restrict__ tout = (float4*)outT;
        float4* __restrict__ uout = (float4*)outU;
        const size_t start  = (size_t)(bid - nCompute) * NTHREADS + threadIdx.x;
        const size_t stride = (size_t)nCopyBlocks * NTHREADS;

        #pragma unroll 4
        for (size_t i = start; i < t4; i += stride)
            __stcs(&tout[i], __ldcs(&tin[i]));
        #pragma unroll 4
        for (size_t i = start; i < u4; i += stride)
            __stcs(&uout[i], __ldcs(&uin[i]));
    }
}

// ---------------------------------------------------------------------------
// Kernel 2: per-row dots + softmax weights; overwrite dependent rows.
// ---------------------------------------------------------------------------
__global__ void __launch_bounds__(NTHREADS)
finalize(const float* __restrict__ text,
         const float* __restrict__ user,
         const void*  __restrict__ uidx,
         const float* __restrict__ bt,
         const float* __restrict__ bg,
         float* __restrict__ outT,
         float* __restrict__ outU,
         int B, long long SC, long long user_rows)
{
    __shared__ float red[3][8];
    __shared__ float wcoef[4];

    const int r   = blockIdx.x;
    const int tid = threadIdx.x;
    const int is64 = detect_is64(uidx, B, user_rows);
    const long long u = load_idx(uidx, r, is64);

    const float* __restrict__ x = text + (size_t)r * SC;
    const float* __restrict__ g = user + (size_t)u * CDIM;

    float pxb = 0.f, pgb = 0.f, pxg = 0.f;
    for (int c = tid; c < CDIM; c += NTHREADS) {
        float xv = x[c], gv = g[c];
        pxb += xv * bt[c];
        pgb += gv * bg[c];
        pxg += xv * gv;
    }
    #pragma unroll
    for (int o = 16; o; o >>= 1) {
        pxb += __shfl_xor_sync(0xffffffffu, pxb, o);
        pgb += __shfl_xor_sync(0xffffffffu, pgb, o);
        pxg += __shfl_xor_sync(0xffffffffu, pxg, o);
    }
    const int warp = tid >> 5, lane = tid & 31;
    if (lane == 0) { red[0][warp] = pxb; red[1][warp] = pgb; red[2][warp] = pxg; }
    __syncthreads();

    if (tid == 0) {
        float sxb = 0.f, sgb = 0.f, sxg = 0.f;
        #pragma unroll
        for (int w = 0; w < 8; w++) { sxb += red[0][w]; sgb += red[1][w]; sxg += red[2][w]; }
        float a  = g_quad[r] + sxb;        // text_ini . text_tmp
        float b  = sxg;                    // graph_ini . text_ini
        float cq = g_quad[QOFF + r] + sgb; // graph_tmp . graph_ini
        float d  = sxg;
        float wa = 1.f / (1.f + expf(b - a));
        float wc = 1.f / (1.f + expf(d - cq));
        wcoef[0] = wa; wcoef[1] = 1.f - wa;
        wcoef[2] = wc; wcoef[3] = 1.f - wc;
    }
    __syncthreads();

    const float wa = wcoef[0], wb = wcoef[1], wc = wcoef[2], wd = wcoef[3];
    if (tid < C4) {
        const float4 xv = ((const float4*)x)[tid];
        const float4 gv = ((const float4*)g)[tid];
        float4 to, uo;
        to.x = wa * xv.x + wb * gv.x;  uo.x = wc * gv.x + wd * xv.x;
        to.y = wa * xv.y + wb * gv.y;  uo.y = wc * gv.y + wd * xv.y;
        to.z = wa * xv.z + wb * gv.z;  uo.z = wc * gv.z + wd * xv.z;
        to.w = wa * xv.w + wb * gv.w;  uo.w = wc * gv.w + wd * xv.w;
        ((float4*)(outT + (size_t)r * SC))[tid]   = to;
        ((float4*)(outU + (size_t)u * CDIM))[tid] = uo;
    }
}

// ---------------------------------------------------------------------------
extern "C" void kernel_launch(void* const* d_in, const int* in_sizes, int n_in,
                              void* d_out, int out_size)
{
    const float* text = (const float*)d_in[0];
    const float* user = (const float*)d_in[1];
    const void*  uidx = d_in[2];
    const float* Wt   = (const float*)d_in[3];
    const float* bt   = (const float*)d_in[4];
    const float* Wg   = (const float*)d_in[5];
    const float* bg   = (const float*)d_in[6];

    const long long text_n = in_sizes[0];
    const long long user_n = in_sizes[1];
    const int B = in_sizes[2];
    const long long SC = text_n / (long long)B;       // S*C
    const long long user_rows = user_n / CDIM;

    float* outT = (float*)d_out;
    float* outU = outT + text_n;

    const int nQ = (B + ROWS_PER_BLOCK - 1) / ROWS_PER_BLOCK;   // 64
    const int nCompute = 2 * nQ;                                // 128
    const int nCopy = 1152;
    const int nTotal = nCompute + nCopy;

    fused_copy_quad<<<nTotal, NTHREADS>>>(text, user, uidx, Wt, Wg,
                                          outT, outU,
                                          B, SC, text_n, user_n, user_rows,
                                          nQ, nCompute, nCopy);
    finalize<<<B, NTHREADS>>>(text, user, uidx, bt, bg,
                              outT, outU, B, SC, user_rows);
}

// round 2
// speedup vs baseline: 1.4043x; 1.4043x over previous
#include <cuda_runtime.h>

#define CDIM 768
#define C4   192          // CDIM/4
#define NTHREADS 256
#define ROWS_PER_WARP 2
#define ROWS_PER_BLOCK 16 // 8 warps * 2 rows
#define QOFF 4096         // scratch stride (max B supported = 4096)
#define INTERLEAVE 6      // every 6th block is a compute block

// scratch for quadratic forms: [0,B) = text quad, [QOFF,QOFF+B) = graph quad
__device__ float g_quad[2 * QOFF];

// user_index may be stored int64 (as declared) or int32 (JAX default x64-off).
__device__ __forceinline__ int detect_is64(const void* uptr, int B, long long nrows) {
    if (B < 2) return 1;
    long long v = ((const long long*)uptr)[B / 2 - 1];
    return (v >= 0 && v < nrows) ? 1 : 0;
}

__device__ __forceinline__ long long load_idx(const void* uptr, int i, int is64) {
    if (is64) return ((const long long*)uptr)[i];
    return (long long)((const int*)uptr)[i];
}

// ---------------------------------------------------------------------------
// Fused kernel: blocks with bid % INTERLEAVE == 0 (and qid < nCompute) compute
// the quadratic forms x^T W^T x into g_quad; all other blocks stream-copy
// text -> outT and all_user_feature -> outU. Interleaving keeps copy traffic
// flowing on every SM in every wave; 3 blocks/SM via launch_bounds.
// ---------------------------------------------------------------------------
__global__ void __launch_bounds__(NTHREADS, 3)
fused_copy_quad(const float* __restrict__ text,
                const float* __restrict__ user,
                const void*  __restrict__ uidx,
                const float* __restrict__ Wt,
                const float* __restrict__ Wg,
                float* __restrict__ outT,
                float* __restrict__ outU,
                int B, long long SC,
                long long text_n, long long user_n,
                long long user_rows,
                int nQ, int nCompute, int nCopyBlocks)
{
    const int bid = blockIdx.x;
    const int qid = bid / INTERLEAVE;
    const bool isComputeBlock = (bid % INTERLEAVE == 0) && (qid < nCompute);

    if (isComputeBlock) {
        // ---------------- quadratic-form blocks ----------------
        const int isGraph = (qid >= nQ) ? 1 : 0;
        const int qb = isGraph ? (qid - nQ) : qid;
        const float* __restrict__ W = isGraph ? Wg : Wt;
        const int warp = threadIdx.x >> 5;
        const int lane = threadIdx.x & 31;
        const int row0 = qb * ROWS_PER_BLOCK + warp * ROWS_PER_WARP;
        const int is64 = detect_is64(uidx, B, user_rows);

        // resident x rows: 2 rows x 24 floats/lane (48 regs)
        float4 xr[ROWS_PER_WARP][6];
        #pragma unroll
        for (int r = 0; r < ROWS_PER_WARP; r++) {
            int row = row0 + r;
            if (row >= B) row = B - 1;  // clamp; store guarded below
            const float4* src;
            if (isGraph) {
                long long u = load_idx(uidx, row, is64);
                src = (const float4*)(user + (size_t)u * CDIM);
            } else {
                src = (const float4*)(text + (size_t)row * SC);
            }
            #pragma unroll
            for (int i = 0; i < 6; i++) xr[r][i] = src[lane + 32 * i];
        }

        float acc[ROWS_PER_WARP] = {0.f, 0.f};

        #pragma unroll
        for (int ij = 0; ij < 6; ij++) {
            for (int jl = 0; jl < 32; jl++) {
                float4 xb[ROWS_PER_WARP];
                #pragma unroll
                for (int r = 0; r < ROWS_PER_WARP; r++) {
                    xb[r].x = __shfl_sync(0xffffffffu, xr[r][ij].x, jl);
                    xb[r].y = __shfl_sync(0xffffffffu, xr[r][ij].y, jl);
                    xb[r].z = __shfl_sync(0xffffffffu, xr[r][ij].z, jl);
                    xb[r].w = __shfl_sync(0xffffffffu, xr[r][ij].w, jl);
                }
                const int j4 = ij * 32 + jl;
                #pragma unroll
                for (int c = 0; c < 4; c++) {
                    const float4* __restrict__ Wrow =
                        (const float4*)(W + (size_t)(4 * j4 + c) * CDIM);
                    float p[ROWS_PER_WARP] = {0.f, 0.f};
                    #pragma unroll
                    for (int i = 0; i < 6; i++) {
                        float4 w = Wrow[lane + 32 * i];
                        #pragma unroll
                        for (int r = 0; r < ROWS_PER_WARP; r++) {
                            p[r] += w.x * xr[r][i].x + w.y * xr[r][i].y
                                  + w.z * xr[r][i].z + w.w * xr[r][i].w;
                        }
                    }
                    #pragma unroll
                    for (int r = 0; r < ROWS_PER_WARP; r++) {
                        float xc = (c == 0) ? xb[r].x : (c == 1) ? xb[r].y
                                 : (c == 2) ? xb[r].z : xb[r].w;
                        acc[r] += xc * p[r];
                    }
                }
            }
        }

        #pragma unroll
        for (int r = 0; r < ROWS_PER_WARP; r++) {
            float v = acc[r];
            v += __shfl_xor_sync(0xffffffffu, v, 16);
            v += __shfl_xor_sync(0xffffffffu, v, 8);
            v += __shfl_xor_sync(0xffffffffu, v, 4);
            v += __shfl_xor_sync(0xffffffffu, v, 2);
            v += __shfl_xor_sync(0xffffffffu, v, 1);
            int row = row0 + r;
            if (lane == 0 && row < B) g_quad[isGraph * QOFF + row] = v;
        }
    } else {
        // ---------------- streaming copy blocks ----------------
        // copy index: number of copy blocks before bid
        const int nCompBefore = (bid / INTERLEAVE < nCompute)
                              ? (bid / INTERLEAVE + 1)
                              : nCompute;
        const int copyId = bid - nCompBefore;

        const size_t t4 = (size_t)text_n >> 2;
        const size_t u4 = (size_t)user_n >> 2;
        const float4* __restrict__ tin  = (const float4*)text;
        const float4* __restrict__ uin  = (const float4*)user;
        float4* __restrict__ tout = (float4*)outT;
        float4* __restrict__ uout = (float4*)outU;
        const size_t stride = (size_t)nCopyBlocks * NTHREADS;

        // 8-deep batched copy for MLP
        {
            size_t i = (size_t)copyId * NTHREADS + threadIdx.x;
            for (; i + 7 * stride < t4; i += 8 * stride) {
                float4 v0 = __ldcs(&tin[i + 0 * stride]);
                float4 v1 = __ldcs(&tin[i + 1 * stride]);
                float4 v2 = __ldcs(&tin[i + 2 * stride]);
                float4 v3 = __ldcs(&tin[i + 3 * stride]);
                float4 v4 = __ldcs(&tin[i + 4 * stride]);
                float4 v5 = __ldcs(&tin[i + 5 * stride]);
                float4 v6 = __ldcs(&tin[i + 6 * stride]);
                float4 v7 = __ldcs(&tin[i + 7 * stride]);
                __stcs(&tout[i + 0 * stride], v0);
                __stcs(&tout[i + 1 * stride], v1);
                __stcs(&tout[i + 2 * stride], v2);
                __stcs(&tout[i + 3 * stride], v3);
                __stcs(&tout[i + 4 * stride], v4);
                __stcs(&tout[i + 5 * stride], v5);
                __stcs(&tout[i + 6 * stride], v6);
                __stcs(&tout[i + 7 * stride], v7);
            }
            for (; i < t4; i += stride)
                __stcs(&tout[i], __ldcs(&tin[i]));
        }
        {
            size_t i = (size_t)copyId * NTHREADS + threadIdx.x;
            for (; i + 7 * stride < u4; i += 8 * stride) {
                float4 v0 = __ldcs(&uin[i + 0 * stride]);
                float4 v1 = __ldcs(&uin[i + 1 * stride]);
                float4 v2 = __ldcs(&uin[i + 2 * stride]);
                float4 v3 = __ldcs(&uin[i + 3 * stride]);
                float4 v4 = __ldcs(&uin[i + 4 * stride]);
                float4 v5 = __ldcs(&uin[i + 5 * stride]);
                float4 v6 = __ldcs(&uin[i + 6 * stride]);
                float4 v7 = __ldcs(&uin[i + 7 * stride]);
                __stcs(&uout[i + 0 * stride], v0);
                __stcs(&uout[i + 1 * stride], v1);
                __stcs(&uout[i + 2 * stride], v2);
                __stcs(&uout[i + 3 * stride], v3);
                __stcs(&uout[i + 4 * stride], v4);
                __stcs(&uout[i + 5 * stride], v5);
                __stcs(&uout[i + 6 * stride], v6);
                __stcs(&uout[i + 7 * stride], v7);
            }
            for (; i < u4; i += stride)
                __stcs(&uout[i], __ldcs(&uin[i]));
        }
    }
}

// ---------------------------------------------------------------------------
// Kernel 2: per-row dots + softmax weights; overwrite dependent rows.
// ---------------------------------------------------------------------------
__global__ void __launch_bounds__(NTHREADS)
finalize(const float* __restrict__ text,
         const float* __restrict__ user,
         const void*  __restrict__ uidx,
         const float* __restrict__ bt,
         const float* __restrict__ bg,
         float* __restrict__ outT,
         float* __restrict__ outU,
         int B, long long SC, long long user_rows)
{
    __shared__ float red[3][8];
    __shared__ float wcoef[4];

    const int r   = blockIdx.x;
    const int tid = threadIdx.x;
    const int is64 = detect_is64(uidx, B, user_rows);
    const long long u = load_idx(uidx, r, is64);

    const float* __restrict__ x = text + (size_t)r * SC;
    const float* __restrict__ g = user + (size_t)u * CDIM;

    float pxb = 0.f, pgb = 0.f, pxg = 0.f;
    for (int c = tid; c < CDIM; c += NTHREADS) {
        float xv = x[c], gv = g[c];
        pxb += xv * bt[c];
        pgb += gv * bg[c];
        pxg += xv * gv;
    }
    #pragma unroll
    for (int o = 16; o; o >>= 1) {
        pxb += __shfl_xor_sync(0xffffffffu, pxb, o);
        pgb += __shfl_xor_sync(0xffffffffu, pgb, o);
        pxg += __shfl_xor_sync(0xffffffffu, pxg, o);
    }
    const int warp = tid >> 5, lane = tid & 31;
    if (lane == 0) { red[0][warp] = pxb; red[1][warp] = pgb; red[2][warp] = pxg; }
    __syncthreads();

    if (tid == 0) {
        float sxb = 0.f, sgb = 0.f, sxg = 0.f;
        #pragma unroll
        for (int w = 0; w < 8; w++) { sxb += red[0][w]; sgb += red[1][w]; sxg += red[2][w]; }
        float a  = g_quad[r] + sxb;        // text_ini . text_tmp
        float b  = sxg;                    // graph_ini . text_ini
        float cq = g_quad[QOFF + r] + sgb; // graph_tmp . graph_ini
        float d  = sxg;
        float wa = 1.f / (1.f + expf(b - a));
        float wc = 1.f / (1.f + expf(d - cq));
        wcoef[0] = wa; wcoef[1] = 1.f - wa;
        wcoef[2] = wc; wcoef[3] = 1.f - wc;
    }
    __syncthreads();

    const float wa = wcoef[0], wb = wcoef[1], wc = wcoef[2], wd = wcoef[3];
    if (tid < C4) {
        const float4 xv = ((const float4*)x)[tid];
        const float4 gv = ((const float4*)g)[tid];
        float4 to, uo;
        to.x = wa * xv.x + wb * gv.x;  uo.x = wc * gv.x + wd * xv.x;
        to.y = wa * xv.y + wb * gv.y;  uo.y = wc * gv.y + wd * xv.y;
        to.z = wa * xv.z + wb * gv.z;  uo.z = wc * gv.z + wd * xv.z;
        to.w = wa * xv.w + wb * gv.w;  uo.w = wc * gv.w + wd * xv.w;
        ((float4*)(outT + (size_t)r * SC))[tid]   = to;
        ((float4*)(outU + (size_t)u * CDIM))[tid] = uo;
    }
}

// ---------------------------------------------------------------------------
extern "C" void kernel_launch(void* const* d_in, const int* in_sizes, int n_in,
                              void* d_out, int out_size)
{
    const float* text = (const float*)d_in[0];
    const float* user = (const float*)d_in[1];
    const void*  uidx = d_in[2];
    const float* Wt   = (const float*)d_in[3];
    const float* bt   = (const float*)d_in[4];
    const float* Wg   = (const float*)d_in[5];
    const float* bg   = (const float*)d_in[6];

    const long long text_n = in_sizes[0];
    const long long user_n = in_sizes[1];
    const int B = in_sizes[2];
    const long long SC = text_n / (long long)B;       // S*C
    const long long user_rows = user_n / CDIM;

    float* outT = (float*)d_out;
    float* outU = outT + text_n;

    const int nQ = (B + ROWS_PER_BLOCK - 1) / ROWS_PER_BLOCK;   // 128
    const int nCompute = 2 * nQ;                                // 256
    const int nCopy = 1280;
    const int nTotal = nCompute + nCopy;                        // 1536

    fused_copy_quad<<<nTotal, NTHREADS>>>(text, user, uidx, Wt, Wg,
                                          outT, outU,
                                          B, SC, text_n, user_n, user_rows,
                                          nQ, nCompute, nCopy);
    finalize<<<B, NTHREADS>>>(text, user, uidx, bt, bg,
                              outT, outU, B, SC, user_rows);
}

// round 3
// speedup vs baseline: 1.7429x; 1.2411x over previous
#include <cuda_runtime.h>

#define CDIM 768
#define C4   192            // CDIM/4
#define NTHREADS 256
#define NBLOCKS  456        // 152 SMs * 3 blocks
#define ROWS_PER_WARP 2
#define ROWS_PER_BLOCK 16   // 8 warps * 2 rows
#define QOFF 4096           // scratch stride (max B supported = 4096)
#define CHUNK4 4096         // float4 per copy chunk (64 KB)

// scratch for quadratic forms: [0,B) = text quad, [QOFF,QOFF+B) = graph quad
__device__ float g_quad[2 * QOFF];
// dynamic work queue state
__device__ unsigned g_ctr;        // next work item
__device__ unsigned g_quadDone;   // completed compute items
__device__ unsigned g_copyDone;   // completed copy chunks

__global__ void init_counters() {
    g_ctr = 0u; g_quadDone = 0u; g_copyDone = 0u;
}

// user_index may be stored int64 (as declared) or int32 (JAX default x64-off).
__device__ __forceinline__ int detect_is64(const void* uptr, int B, long long nrows) {
    if (B < 2) return 1;
    long long v = ((const long long*)uptr)[B / 2 - 1];
    return (v >= 0 && v < nrows) ? 1 : 0;
}

__device__ __forceinline__ long long load_idx(const void* uptr, int i, int is64) {
    if (is64) return ((const long long*)uptr)[i];
    return (long long)((const int*)uptr)[i];
}

// ---------------------------------------------------------------------------
// Mega kernel. Work items (one global atomic counter):
//   [0, CQ)                    : quadratic-form items (16 rows each)
//   [CQ, CQ+NCHUNK)            : 64KB copy chunks over concat(text, user)
//   [CQ+NCHUNK, +NFIN)         : finalize items (8 rows each), spin until
//                                quad + copy complete, then overwrite rows.
// ---------------------------------------------------------------------------
__global__ void __launch_bounds__(NTHREADS, 3)
mega(const float* __restrict__ text,
     const float* __restrict__ user,
     const void*  __restrict__ uidx,
     const float* __restrict__ Wt,
     const float* __restrict__ bt,
     const float* __restrict__ Wg,
     const float* __restrict__ bg,
     float* __restrict__ outAll,      // outT (text_n) then outU (user_n)
     int B, long long SC,
     long long text_n, long long user_n,
     long long user_rows,
     unsigned nQ, unsigned CQ, unsigned NCHUNK, unsigned TOTAL)
{
    __shared__ unsigned s_item;
    const int tid  = threadIdx.x;
    const int warp = tid >> 5;
    const int lane = tid & 31;

    const size_t t4   = (size_t)text_n >> 2;
    const size_t tot4 = (size_t)(text_n + user_n) >> 2;
    const float4* __restrict__ tin = (const float4*)text;
    const float4* __restrict__ uin = (const float4*)user;
    float4* __restrict__ dall = (float4*)outAll;

    // first grab
    if (tid == 0) s_item = atomicAdd(&g_ctr, 1u);
    __syncthreads();
    unsigned item = s_item;

    // ---------------- phase 1: quadratic-form items ----------------
    while (item < CQ) {
        const int isGraph = (item >= nQ) ? 1 : 0;
        const int qb = isGraph ? (int)(item - nQ) : (int)item;
        const float* __restrict__ W = isGraph ? Wg : Wt;
        const int row0 = qb * ROWS_PER_BLOCK + warp * ROWS_PER_WARP;
        const int is64 = detect_is64(uidx, B, user_rows);

        float4 xr[ROWS_PER_WARP][6];
        #pragma unroll
        for (int r = 0; r < ROWS_PER_WARP; r++) {
            int row = row0 + r;
            if (row >= B) row = B - 1;          // clamp; store guarded below
            const float4* src;
            if (isGraph) {
                long long u = load_idx(uidx, row, is64);
                src = (const float4*)(user + (size_t)u * CDIM);
            } else {
                src = (const float4*)(text + (size_t)row * SC);
            }
            #pragma unroll
            for (int i = 0; i < 6; i++) xr[r][i] = src[lane + 32 * i];
        }

        float acc[ROWS_PER_WARP] = {0.f, 0.f};
        #pragma unroll
        for (int ij = 0; ij < 6; ij++) {
            for (int jl = 0; jl < 32; jl++) {
                float4 xb[ROWS_PER_WARP];
                #pragma unroll
                for (int r = 0; r < ROWS_PER_WARP; r++) {
                    xb[r].x = __shfl_sync(0xffffffffu, xr[r][ij].x, jl);
                    xb[r].y = __shfl_sync(0xffffffffu, xr[r][ij].y, jl);
                    xb[r].z = __shfl_sync(0xffffffffu, xr[r][ij].z, jl);
                    xb[r].w = __shfl_sync(0xffffffffu, xr[r][ij].w, jl);
                }
                const int j4 = ij * 32 + jl;
                #pragma unroll
                for (int c = 0; c < 4; c++) {
                    const float4* __restrict__ Wrow =
                        (const float4*)(W + (size_t)(4 * j4 + c) * CDIM);
                    float p[ROWS_PER_WARP] = {0.f, 0.f};
                    #pragma unroll
                    for (int i = 0; i < 6; i++) {
                        float4 w = Wrow[lane + 32 * i];
                        #pragma unroll
                        for (int r = 0; r < ROWS_PER_WARP; r++) {
                            p[r] += w.x * xr[r][i].x + w.y * xr[r][i].y
                                  + w.z * xr[r][i].z + w.w * xr[r][i].w;
                        }
                    }
                    #pragma unroll
                    for (int r = 0; r < ROWS_PER_WARP; r++) {
                        float xc = (c == 0) ? xb[r].x : (c == 1) ? xb[r].y
                                 : (c == 2) ? xb[r].z : xb[r].w;
                        acc[r] += xc * p[r];
                    }
                }
            }
        }

        #pragma unroll
        for (int r = 0; r < ROWS_PER_WARP; r++) {
            float v = acc[r];
            v += __shfl_xor_sync(0xffffffffu, v, 16);
            v += __shfl_xor_sync(0xffffffffu, v, 8);
            v += __shfl_xor_sync(0xffffffffu, v, 4);
            v += __shfl_xor_sync(0xffffffffu, v, 2);
            v += __shfl_xor_sync(0xffffffffu, v, 1);
            int row = row0 + r;
            if (lane == 0 && row < B) g_quad[isGraph * QOFF + row] = v;
        }

        __threadfence();
        __syncthreads();
        if (tid == 0) {
            atomicAdd(&g_quadDone, 1u);
            s_item = atomicAdd(&g_ctr, 1u);
        }
        __syncthreads();
        item = s_item;
    }

    // ---------------- phase 2: copy chunks (pipelined grab) ----------------
    while (item < CQ + NCHUNK) {
        const unsigned chunk = item - CQ;
        __syncthreads();                      // s_item reuse protection
        if (tid == 0) s_item = atomicAdd(&g_ctr, 1u);   // prefetch next

        size_t base = (size_t)chunk * CHUNK4 + tid;
        // 16 float4 per thread as two 8-deep batches
        #pragma unroll
        for (int half = 0; half < 2; half++) {
            float4 v[8];
            size_t idx0 = base + (size_t)half * 8 * NTHREADS;
            #pragma unroll
            for (int j = 0; j < 8; j++) {
                size_t idx = idx0 + (size_t)j * NTHREADS;
                if (idx < tot4) {
                    v[j] = (idx < t4) ? __ldcs(&tin[idx])
                                      : __ldcs(&uin[idx - t4]);
                }
            }
            #pragma unroll
            for (int j = 0; j < 8; j++) {
                size_t idx = idx0 + (size_t)j * NTHREADS;
                if (idx < tot4) __stcs(&dall[idx], v[j]);
            }
        }

        __threadfence();
        __syncthreads();                      // stores fenced by all threads
        if (tid == 0) atomicAdd(&g_copyDone, 1u);
        item = s_item;
    }

    // ---------------- phase 3: finalize items ----------------
    while (item < TOTAL) {
        const unsigned fitem = item - CQ - NCHUNK;

        // wait for all quad + copy work to be globally visible
        if (tid == 0) {
            while (*(volatile unsigned*)&g_quadDone < CQ)     __nanosleep(200);
            while (*(volatile unsigned*)&g_copyDone < NCHUNK) __nanosleep(200);
        }
        __syncthreads();
        __threadfence();

        const int is64 = detect_is64(uidx, B, user_rows);
        const int r = (int)fitem * 8 + warp;
        if (r < B) {
            long long u = load_idx(uidx, r, is64);
            const float4* __restrict__ x4  = (const float4*)(text + (size_t)r * SC);
            const float4* __restrict__ g4  = (const float4*)(user + (size_t)u * CDIM);
            const float4* __restrict__ bt4 = (const float4*)bt;
            const float4* __restrict__ bg4 = (const float4*)bg;

            float4 xs[6], gs[6];
            float pxb = 0.f, pgb = 0.f, pxg = 0.f;
            #pragma unroll
            for (int k = 0; k < 6; k++) {
                xs[k] = x4[lane + 32 * k];
                gs[k] = g4[lane + 32 * k];
                float4 bv = bt4[lane + 32 * k];
                float4 gv = bg4[lane + 32 * k];
                pxb += xs[k].x * bv.x + xs[k].y * bv.y + xs[k].z * bv.z + xs[k].w * bv.w;
                pgb += gs[k].x * gv.x + gs[k].y * gv.y + gs[k].z * gv.z + gs[k].w * gv.w;
                pxg += xs[k].x * gs[k].x + xs[k].y * gs[k].y + xs[k].z * gs[k].z + xs[k].w * gs[k].w;
            }
            #pragma unroll
            for (int o = 16; o; o >>= 1) {
                pxb += __shfl_xor_sync(0xffffffffu, pxb, o);
                pgb += __shfl_xor_sync(0xffffffffu, pgb, o);
                pxg += __shfl_xor_sync(0xffffffffu, pxg, o);
            }
            float wa, wc;
            if (lane == 0) {
                float a  = g_quad[r] + pxb;          // text_ini . text_tmp
                float cq = g_quad[QOFF + r] + pgb;   // graph_tmp . graph_ini
                float bq = pxg;                      // graph_ini . text_ini
                wa = 1.f / (1.f + expf(bq - a));
                wc = 1.f / (1.f + expf(bq - cq));
            }
            wa = __shfl_sync(0xffffffffu, wa, 0);
            wc = __shfl_sync(0xffffffffu, wc, 0);
            const float wb = 1.f - wa, wd = 1.f - wc;

            float4* __restrict__ oT = (float4*)(outAll + (size_t)r * SC);
            float4* __restrict__ oU = (float4*)(outAll + text_n + (size_t)u * CDIM);
            #pragma unroll
            for (int k = 0; k < 6; k++) {
                float4 to, uo;
                to.x = wa * xs[k].x + wb * gs[k].x;  uo.x = wc * gs[k].x + wd * xs[k].x;
                to.y = wa * xs[k].y + wb * gs[k].y;  uo.y = wc * gs[k].y + wd * xs[k].y;
                to.z = wa * xs[k].z + wb * gs[k].z;  uo.z = wc * gs[k].z + wd * xs[k].z;
                to.w = wa * xs[k].w + wb * gs[k].w;  uo.w = wc * gs[k].w + wd * xs[k].w;
                oT[lane + 32 * k] = to;
                oU[lane + 32 * k] = uo;
            }
        }

        __syncthreads();
        if (tid == 0) s_item = atomicAdd(&g_ctr, 1u);
        __syncthreads();
        item = s_item;
    }
}

// ---------------------------------------------------------------------------
extern "C" void kernel_launch(void* const* d_in, const int* in_sizes, int n_in,
                              void* d_out, int out_size)
{
    const float* text = (const float*)d_in[0];
    const float* user = (const float*)d_in[1];
    const void*  uidx = d_in[2];
    const float* Wt   = (const float*)d_in[3];
    const float* bt   = (const float*)d_in[4];
    const float* Wg   = (const float*)d_in[5];
    const float* bg   = (const float*)d_in[6];

    const long long text_n = in_sizes[0];
    const long long user_n = in_sizes[1];
    const int B = in_sizes[2];
    const long long SC = text_n / (long long)B;       // S*C
    const long long user_rows = user_n / CDIM;

    const unsigned nQ = (unsigned)((B + ROWS_PER_BLOCK - 1) / ROWS_PER_BLOCK); // 128
    const unsigned CQ = 2 * nQ;                                                // 256
    const size_t tot4 = (size_t)(text_n + user_n) >> 2;
    const unsigned NCHUNK = (unsigned)((tot4 + CHUNK4 - 1) / CHUNK4);
    const unsigned NFIN = (unsigned)((B + 7) / 8);
    const unsigned TOTAL = CQ + NCHUNK + NFIN;

    init_counters<<<1, 1>>>();
    mega<<<NBLOCKS, NTHREADS>>>(text, user, uidx, Wt, bt, Wg, bg,
                                (float*)d_out,
                                B, SC, text_n, user_n, user_rows,
                                nQ, CQ, NCHUNK, TOTAL);
}

// round 4
// speedup vs baseline: 2.3375x; 1.3412x over previous
#include <cuda_runtime.h>

#define CDIM  768
#define CDIM4 192           // CDIM/4
#define NTHREADS 256
#define NBLOCKS  304        // 152 SMs * 2 blocks
#define TM 128
#define TN 128
#define TK 32
#define KTILES (CDIM / TK)  // 24
#define JTILES (CDIM / TN)  // 6
#define QOFF 4096           // scratch stride (max B = 4096)
#define CHUNK4 4096         // float4 per copy chunk (64 KB)
#define TMP (TM + 4)        // padded smem row

// quadratic-form scratch: [0,B) text, [QOFF,QOFF+B) graph. MUST be zero at
// kernel entry: zero-initialized at load; re-zeroed by last-exiting block.
__device__ float g_quad[2 * QOFF];
__device__ unsigned g_ctr;        // work-queue head
__device__ unsigned g_quadDone;   // completed GEMM items
__device__ unsigned g_copyDone;   // completed copy chunks
__device__ unsigned g_exit;       // exited blocks

// user_index may be int64 (declared) or int32 (JAX x64-off default).
__device__ __forceinline__ int detect_is64(const void* uptr, int B, long long nrows) {
    if (B < 2) return 1;
    long long v = ((const long long*)uptr)[B / 2 - 1];
    return (v >= 0 && v < nrows) ? 1 : 0;
}
__device__ __forceinline__ long long load_idx(const void* uptr, int i, int is64) {
    if (is64) return ((const long long*)uptr)[i];
    return (long long)((const int*)uptr)[i];
}

// ---- packed fp32x2 helpers (SASS FFMA2; ptxas never auto-fuses) ----
__device__ __forceinline__ unsigned long long dup2(float a) {
    unsigned long long d; unsigned ai = __float_as_uint(a);
    asm("mov.b64 %0, {%1, %1};" : "=l"(d) : "r"(ai));
    return d;
}
__device__ __forceinline__ void fma2(unsigned long long& acc,
                                     unsigned long long a, unsigned long long b) {
    asm("fma.rn.f32x2 %0, %1, %2, %0;" : "+l"(acc) : "l"(a), "l"(b));
}
__device__ __forceinline__ float2 unpack2(unsigned long long v) {
    float2 r;
    asm("mov.b64 {%0, %1}, %2;" : "=f"(r.x), "=f"(r.y) : "l"(v));
    return r;
}

// ---------------------------------------------------------------------------
// Single mega kernel, dynamic work queue:
//   [0, NG)            : GEMM tiles (128x128x768 bilinear-form partial sums)
//   [NG, NG+NCHUNK)    : 64KB streaming copy chunks over concat(text, user)
//   [.., +NFIN)        : finalize items (8 rows), wait quad+copy complete
// Last block to exit resets queue state + re-zeroes g_quad for next replay.
// ---------------------------------------------------------------------------
__global__ void __launch_bounds__(NTHREADS, 2)
mega(const float* __restrict__ text,
     const float* __restrict__ user,
     const void*  __restrict__ uidx,
     const float* __restrict__ Wt,
     const float* __restrict__ bt,
     const float* __restrict__ Wg,
     const float* __restrict__ bg,
     float* __restrict__ outAll,           // outT (text_n) then outU (user_n)
     int B, long long SC,
     long long text_n, long long user_n,
     long long user_rows,
     unsigned NG, unsigned NCHUNK, unsigned TOTAL)
{
    __shared__ float As[TK][TMP];
    __shared__ float Bs[TK][TMP];
    __shared__ unsigned s_item;

    const int tid  = threadIdx.x;
    const int warp = tid >> 5;
    const int lane = tid & 31;
    const int tx   = tid & 15;    // j-fragment index
    const int ty   = tid >> 4;    // row-fragment index

    const size_t t4   = (size_t)text_n >> 2;
    const size_t tot4 = (size_t)(text_n + user_n) >> 2;
    const float4* __restrict__ tin = (const float4*)text;
    const float4* __restrict__ uin = (const float4*)user;
    float4* __restrict__ dall = (float4*)outAll;

    const unsigned perM = (unsigned)((B / TM) * JTILES);   // GEMM items per matrix

    if (tid == 0) s_item = atomicAdd(&g_ctr, 1u);
    __syncthreads();
    unsigned item = s_item;

    const int is64 = detect_is64(uidx, B, user_rows);

    // ================= phase 1: GEMM bilinear-form tiles =================
    while (item < NG) {
        const int isG = (item >= perM) ? 1 : 0;
        const int qq  = isG ? (int)(item - perM) : (int)item;
        const int mt  = qq / JTILES;
        const int jt  = qq % JTILES;
        const int row0 = mt * TM;
        const int j0   = jt * TN;
        const float* __restrict__ Wm = isG ? Wg : Wt;

        unsigned long long acc[8][4];
        #pragma unroll
        for (int i = 0; i < 8; i++)
            #pragma unroll
            for (int j = 0; j < 4; j++) acc[i][j] = 0ull;

        for (int kt = 0; kt < KTILES; kt++) {
            const int kb4 = kt * (TK / 4);
            __syncthreads();     // previous iter finished reading smem
            // stage A (x rows) and B (W rows) tiles, k-major transposed
            #pragma unroll
            for (int it = 0; it < 4; it++) {
                const int f  = it * NTHREADS + tid;   // 0..1023
                const int r  = f >> 3;                // 0..127
                const int qd = f & 7;                 // float4 within 32-k row
                const float* arow;
                if (isG) {
                    long long u = load_idx(uidx, row0 + r, is64);
                    arow = user + (size_t)u * CDIM;
                } else {
                    arow = text + (size_t)(row0 + r) * SC;
                }
                const float4 va = __ldg(&((const float4*)arow)[kb4 + qd]);
                const float4 vb = __ldg(&((const float4*)(Wm + (size_t)(j0 + r) * CDIM))[kb4 + qd]);
                const int k0 = qd * 4;
                As[k0 + 0][r] = va.x; As[k0 + 1][r] = va.y;
                As[k0 + 2][r] = va.z; As[k0 + 3][r] = va.w;
                Bs[k0 + 0][r] = vb.x; Bs[k0 + 1][r] = vb.y;
                Bs[k0 + 2][r] = vb.z; Bs[k0 + 3][r] = vb.w;
            }
            __syncthreads();

            #pragma unroll 8
            for (int k = 0; k < TK; k++) {
                const float4 a0 = *(const float4*)&As[k][ty * 8];
                const float4 a1 = *(const float4*)&As[k][ty * 8 + 4];
                const float4 b0 = *(const float4*)&Bs[k][tx * 8];
                const float4 b1 = *(const float4*)&Bs[k][tx * 8 + 4];
                unsigned long long bp[4];
                {
                    float2 t0 = make_float2(b0.x, b0.y), t1 = make_float2(b0.z, b0.w);
                    float2 t2 = make_float2(b1.x, b1.y), t3 = make_float2(b1.z, b1.w);
                    bp[0] = *(unsigned long long*)&t0; bp[1] = *(unsigned long long*)&t1;
                    bp[2] = *(unsigned long long*)&t2; bp[3] = *(unsigned long long*)&t3;
                }
                const float av[8] = {a0.x, a0.y, a0.z, a0.w, a1.x, a1.y, a1.z, a1.w};
                #pragma unroll
                for (int ii = 0; ii < 8; ii++) {
                    const unsigned long long ad = dup2(av[ii]);
                    #pragma unroll
                    for (int jp = 0; jp < 4; jp++) fma2(acc[ii][jp], ad, bp[jp]);
                }
            }
        }

        // epilogue: s_r += sum_j P[r,j] * x[r,j], reduce over tx, atomicAdd
        #pragma unroll
        for (int ii = 0; ii < 8; ii++) {
            const int r = row0 + ty * 8 + ii;
            const float* xrow;
            if (isG) {
                long long u = load_idx(uidx, r, is64);
                xrow = user + (size_t)u * CDIM;
            } else {
                xrow = text + (size_t)r * SC;
            }
            const float4 xa = __ldg(&((const float4*)xrow)[(j0 >> 2) + tx * 2]);
            const float4 xb = __ldg(&((const float4*)xrow)[(j0 >> 2) + tx * 2 + 1]);
            const float2 p0 = unpack2(acc[ii][0]);
            const float2 p1 = unpack2(acc[ii][1]);
            const float2 p2 = unpack2(acc[ii][2]);
            const float2 p3 = unpack2(acc[ii][3]);
            float s = p0.x * xa.x + p0.y * xa.y + p1.x * xa.z + p1.y * xa.w
                    + p2.x * xb.x + p2.y * xb.y + p3.x * xb.z + p3.y * xb.w;
            #pragma unroll
            for (int o = 8; o; o >>= 1) s += __shfl_xor_sync(0xffffffffu, s, o);
            if (tx == 0) atomicAdd(&g_quad[isG * QOFF + r], s);
        }

        __threadfence();
        __syncthreads();
        if (tid == 0) {
            atomicAdd(&g_quadDone, 1u);
            s_item = atomicAdd(&g_ctr, 1u);
        }
        __syncthreads();
        item = s_item;
    }

    // ================= phase 2: streaming copy chunks =================
    while (item < NG + NCHUNK) {
        const unsigned chunk = item - NG;
        __syncthreads();
        if (tid == 0) s_item = atomicAdd(&g_ctr, 1u);   // prefetch next item

        const size_t base = (size_t)chunk * CHUNK4 + tid;
        #pragma unroll
        for (int half = 0; half < 2; half++) {
            float4 v[8];
            const size_t idx0 = base + (size_t)half * 8 * NTHREADS;
            #pragma unroll
            for (int j = 0; j < 8; j++) {
                const size_t idx = idx0 + (size_t)j * NTHREADS;
                if (idx < tot4)
                    v[j] = (idx < t4) ? __ldcs(&tin[idx]) : __ldcs(&uin[idx - t4]);
            }
            #pragma unroll
            for (int j = 0; j < 8; j++) {
                const size_t idx = idx0 + (size_t)j * NTHREADS;
                if (idx < tot4) __stcs(&dall[idx], v[j]);
            }
        }

        __threadfence();
        __syncthreads();
        if (tid == 0) atomicAdd(&g_copyDone, 1u);
        item = s_item;
    }

    // ================= phase 3: finalize rows =================
    while (item < TOTAL) {
        const unsigned fitem = item - NG - NCHUNK;

        if (tid == 0) {
            while (*(volatile unsigned*)&g_quadDone < NG)     __nanosleep(200);
            while (*(volatile unsigned*)&g_copyDone < NCHUNK) __nanosleep(200);
        }
        __syncthreads();
        __threadfence();

        const int r = (int)fitem * 8 + warp;
        if (r < B) {
            long long u = load_idx(uidx, r, is64);
            const float4* __restrict__ x4  = (const float4*)(text + (size_t)r * SC);
            const float4* __restrict__ g4  = (const float4*)(user + (size_t)u * CDIM);
            const float4* __restrict__ bt4 = (const float4*)bt;
            const float4* __restrict__ bg4 = (const float4*)bg;

            float4 xs[6], gs[6];
            float pxb = 0.f, pgb = 0.f, pxg = 0.f;
            #pragma unroll
            for (int k = 0; k < 6; k++) {
                xs[k] = x4[lane + 32 * k];
                gs[k] = g4[lane + 32 * k];
                const float4 bv = bt4[lane + 32 * k];
                const float4 gv = bg4[lane + 32 * k];
                pxb += xs[k].x * bv.x + xs[k].y * bv.y + xs[k].z * bv.z + xs[k].w * bv.w;
                pgb += gs[k].x * gv.x + gs[k].y * gv.y + gs[k].z * gv.z + gs[k].w * gv.w;
                pxg += xs[k].x * gs[k].x + xs[k].y * gs[k].y + xs[k].z * gs[k].z + xs[k].w * gs[k].w;
            }
            #pragma unroll
            for (int o = 16; o; o >>= 1) {
                pxb += __shfl_xor_sync(0xffffffffu, pxb, o);
                pgb += __shfl_xor_sync(0xffffffffu, pgb, o);
                pxg += __shfl_xor_sync(0xffffffffu, pxg, o);
            }
            float wa, wc;
            if (lane == 0) {
                const float a  = g_quad[r] + pxb;          // text_ini . text_tmp
                const float cq = g_quad[QOFF + r] + pgb;   // graph_tmp . graph_ini
                const float bq = pxg;                      // graph_ini . text_ini
                wa = 1.f / (1.f + expf(bq - a));
                wc = 1.f / (1.f + expf(bq - cq));
            }
            wa = __shfl_sync(0xffffffffu, wa, 0);
            wc = __shfl_sync(0xffffffffu, wc, 0);
            const float wb = 1.f - wa, wd = 1.f - wc;

            float4* __restrict__ oT = (float4*)(outAll + (size_t)r * SC);
            float4* __restrict__ oU = (float4*)(outAll + text_n + (size_t)u * CDIM);
            #pragma unroll
            for (int k = 0; k < 6; k++) {
                float4 to, uo;
                to.x = wa * xs[k].x + wb * gs[k].x;  uo.x = wc * gs[k].x + wd * xs[k].x;
                to.y = wa * xs[k].y + wb * gs[k].y;  uo.y = wc * gs[k].y + wd * xs[k].y;
                to.z = wa * xs[k].z + wb * gs[k].z;  uo.z = wc * gs[k].z + wd * xs[k].z;
                to.w = wa * xs[k].w + wb * gs[k].w;  uo.w = wc * gs[k].w + wd * xs[k].w;
                oT[lane + 32 * k] = to;
                oU[lane + 32 * k] = uo;
            }
        }

        __syncthreads();
        if (tid == 0) s_item = atomicAdd(&g_ctr, 1u);
        __syncthreads();
        item = s_item;
    }

    // ================= exit: last block resets state for next replay ======
    __syncthreads();
    if (tid == 0) {
        const unsigned t = atomicAdd(&g_exit, 1u);
        s_item = (t == gridDim.x - 1) ? 1u : 0u;
    }
    __syncthreads();
    if (s_item) {
        for (int i = tid; i < 2 * QOFF; i += NTHREADS) g_quad[i] = 0.f;
        __syncthreads();
        if (tid == 0) {
            __threadfence();
            g_quadDone = 0u; g_copyDone = 0u; g_ctr = 0u;
            __threadfence();
            g_exit = 0u;
        }
    }
}

// ---------------------------------------------------------------------------
extern "C" void kernel_launch(void* const* d_in, const int* in_sizes, int n_in,
                              void* d_out, int out_size)
{
    const float* text = (const float*)d_in[0];
    const float* user = (const float*)d_in[1];
    const void*  uidx = d_in[2];
    const float* Wt   = (const float*)d_in[3];
    const float* bt   = (const float*)d_in[4];
    const float* Wg   = (const float*)d_in[5];
    const float* bg   = (const float*)d_in[6];

    const long long text_n = in_sizes[0];
    const long long user_n = in_sizes[1];
    const int B = in_sizes[2];
    const long long SC = text_n / (long long)B;   // S*C
    const long long user_rows = user_n / CDIM;

    const unsigned perM = (unsigned)((B / TM) * JTILES);   // 96
    const unsigned NG = 2 * perM;                           // 192
    const size_t tot4 = (size_t)(text_n + user_n) >> 2;
    const unsigned NCHUNK = (unsigned)((tot4 + CHUNK4 - 1) / CHUNK4);
    const unsigned NFIN = (unsigned)((B + 7) / 8);
    const unsigned TOTAL = NG + NCHUNK + NFIN;

    mega<<<NBLOCKS, NTHREADS>>>(text, user, uidx, Wt, bt, Wg, bg,
                                (float*)d_out,
                                B, SC, text_n, user_n, user_rows,
                                NG, NCHUNK, TOTAL);
}

// round 5
// speedup vs baseline: 2.3802x; 1.0183x over previous
#include <cuda_runtime.h>

#define CDIM  768
#define CDIM4 192           // CDIM/4
#define NTHREADS 256
#define NBLOCKS  304        // 152 SMs * 2 blocks
#define TM 128
#define TN 128
#define TK 32
#define KTILES (CDIM / TK)  // 24
#define JTILES (CDIM / TN)  // 6
#define QOFF 4096           // scratch stride (max B = 4096)
#define CHUNK4 4096         // float4 per copy chunk (64 KB)
#define TMP (TM + 4)        // padded smem row

// quadratic-form scratch: [0,B) text, [QOFF,QOFF+B) graph. MUST be zero at
// kernel entry: zero-initialized at load; re-zeroed by last-exiting block.
__device__ float g_quad[2 * QOFF];
__device__ unsigned g_ctr;        // work-queue head
__device__ unsigned g_quadDone;   // completed GEMM items
__device__ unsigned g_copyDone;   // completed copy chunks
__device__ unsigned g_exit;       // exited blocks

// user_index may be int64 (declared) or int32 (JAX x64-off default).
__device__ __forceinline__ int detect_is64(const void* uptr, int B, long long nrows) {
    if (B < 2) return 1;
    long long v = ((const long long*)uptr)[B / 2 - 1];
    return (v >= 0 && v < nrows) ? 1 : 0;
}
__device__ __forceinline__ long long load_idx(const void* uptr, int i, int is64) {
    if (is64) return ((const long long*)uptr)[i];
    return (long long)((const int*)uptr)[i];
}

// ---- packed fp32x2 helpers (SASS FFMA2; ptxas never auto-fuses) ----
__device__ __forceinline__ unsigned long long dup2(float a) {
    unsigned long long d; unsigned ai = __float_as_uint(a);
    asm("mov.b64 %0, {%1, %1};" : "=l"(d) : "r"(ai));
    return d;
}
__device__ __forceinline__ void fma2(unsigned long long& acc,
                                     unsigned long long a, unsigned long long b) {
    asm("fma.rn.f32x2 %0, %1, %2, %0;" : "+l"(acc) : "l"(a), "l"(b));
}
__device__ __forceinline__ float2 unpack2(unsigned long long v) {
    float2 r;
    asm("mov.b64 {%0, %1}, %2;" : "=f"(r.x), "=f"(r.y) : "l"(v));
    return r;
}

// ---------------------------------------------------------------------------
// Single mega kernel, dynamic work queue. Items [0, NITEMS) are mixed:
//   i % P == 0 && i/P < NG  -> GEMM tile i/P   (spread over first ~half)
//   otherwise               -> copy chunk (i - #gemm items before i)
// Items [NITEMS, NITEMS+NFIN) -> finalize (wait for quad + copy complete).
// Last exiting block resets queue state + re-zeroes g_quad for next replay.
// ---------------------------------------------------------------------------
__global__ void __launch_bounds__(NTHREADS, 2)
mega(const float* __restrict__ text,
     const float* __restrict__ user,
     const void*  __restrict__ uidx,
     const float* __restrict__ Wt,
     const float* __restrict__ bt,
     const float* __restrict__ Wg,
     const float* __restrict__ bg,
     float* __restrict__ outAll,           // outT (text_n) then outU (user_n)
     int B, long long SC,
     long long text_n, long long user_n,
     long long user_rows,
     unsigned NG, unsigned P, unsigned NITEMS,
     unsigned NCHUNK, unsigned TCHUNK, unsigned TOTAL)
{
    __shared__ float As[TK][TMP];
    __shared__ float Bs[TK][TMP];
    __shared__ unsigned s_item;

    const int tid  = threadIdx.x;
    const int warp = tid >> 5;
    const int lane = tid & 31;
    const int tx   = tid & 15;    // j-fragment index
    const int ty   = tid >> 4;    // row-fragment index

    const size_t t4   = (size_t)text_n >> 2;
    const size_t tot4 = (size_t)(text_n + user_n) >> 2;
    const float4* __restrict__ tin = (const float4*)text;
    const float4* __restrict__ uin = (const float4*)user;
    float4* __restrict__ dall = (float4*)outAll;

    const unsigned perM = NG >> 1;          // GEMM items per matrix

    if (tid == 0) s_item = atomicAdd(&g_ctr, 1u);
    __syncthreads();
    unsigned item = s_item;

    const int is64 = detect_is64(uidx, B, user_rows);

    while (item < TOTAL) {
        unsigned g = item / P;
        bool isGemm = (item < NITEMS) && (item - g * P == 0u) && (g < NG);

        if (isGemm) {
            // ================= GEMM bilinear-form tile =================
            const int isG = (g >= perM) ? 1 : 0;
            const int qq  = isG ? (int)(g - perM) : (int)g;
            const int mt  = qq / JTILES;
            const int jt  = qq % JTILES;
            const int row0 = mt * TM;
            const int j0   = jt * TN;
            const float* __restrict__ Wm = isG ? Wg : Wt;

            unsigned long long acc[8][4];
            #pragma unroll
            for (int i = 0; i < 8; i++)
                #pragma unroll
                for (int j = 0; j < 4; j++) acc[i][j] = 0ull;

            for (int kt = 0; kt < KTILES; kt++) {
                const int kb4 = kt * (TK / 4);
                __syncthreads();
                #pragma unroll
                for (int it = 0; it < 4; it++) {
                    const int f  = it * NTHREADS + tid;
                    const int r  = f >> 3;
                    const int qd = f & 7;
                    int rr = row0 + r; if (rr >= B) rr = B - 1;
                    const float* arow;
                    if (isG) {
                        long long u = load_idx(uidx, rr, is64);
                        arow = user + (size_t)u * CDIM;
                    } else {
                        arow = text + (size_t)rr * SC;
                    }
                    const float4 va = __ldg(&((const float4*)arow)[kb4 + qd]);
                    const float4 vb = __ldg(&((const float4*)(Wm + (size_t)(j0 + r) * CDIM))[kb4 + qd]);
                    const int k0 = qd * 4;
                    As[k0 + 0][r] = va.x; As[k0 + 1][r] = va.y;
                    As[k0 + 2][r] = va.z; As[k0 + 3][r] = va.w;
                    Bs[k0 + 0][r] = vb.x; Bs[k0 + 1][r] = vb.y;
                    Bs[k0 + 2][r] = vb.z; Bs[k0 + 3][r] = vb.w;
                }
                __syncthreads();

                #pragma unroll 8
                for (int k = 0; k < TK; k++) {
                    const float4 a0 = *(const float4*)&As[k][ty * 8];
                    const float4 a1 = *(const float4*)&As[k][ty * 8 + 4];
                    const float4 b0 = *(const float4*)&Bs[k][tx * 8];
                    const float4 b1 = *(const float4*)&Bs[k][tx * 8 + 4];
                    unsigned long long bp[4];
                    {
                        float2 t0 = make_float2(b0.x, b0.y), t1 = make_float2(b0.z, b0.w);
                        float2 t2 = make_float2(b1.x, b1.y), t3 = make_float2(b1.z, b1.w);
                        bp[0] = *(unsigned long long*)&t0; bp[1] = *(unsigned long long*)&t1;
                        bp[2] = *(unsigned long long*)&t2; bp[3] = *(unsigned long long*)&t3;
                    }
                    const float av[8] = {a0.x, a0.y, a0.z, a0.w, a1.x, a1.y, a1.z, a1.w};
                    #pragma unroll
                    for (int ii = 0; ii < 8; ii++) {
                        const unsigned long long ad = dup2(av[ii]);
                        #pragma unroll
                        for (int jp = 0; jp < 4; jp++) fma2(acc[ii][jp], ad, bp[jp]);
                    }
                }
            }

            // epilogue: s_r += sum_j P[r,j]*x[r,j]; reduce over tx; atomicAdd
            #pragma unroll
            for (int ii = 0; ii < 8; ii++) {
                const int r = row0 + ty * 8 + ii;
                const int rr = (r < B) ? r : (B - 1);
                const float* xrow;
                if (isG) {
                    long long u = load_idx(uidx, rr, is64);
                    xrow = user + (size_t)u * CDIM;
                } else {
                    xrow = text + (size_t)rr * SC;
                }
                const float4 xa = __ldg(&((const float4*)xrow)[(j0 >> 2) + tx * 2]);
                const float4 xb = __ldg(&((const float4*)xrow)[(j0 >> 2) + tx * 2 + 1]);
                const float2 p0 = unpack2(acc[ii][0]);
                const float2 p1 = unpack2(acc[ii][1]);
                const float2 p2 = unpack2(acc[ii][2]);
                const float2 p3 = unpack2(acc[ii][3]);
                float s = p0.x * xa.x + p0.y * xa.y + p1.x * xa.z + p1.y * xa.w
                        + p2.x * xb.x + p2.y * xb.y + p3.x * xb.z + p3.y * xb.w;
                #pragma unroll
                for (int o = 8; o; o >>= 1) s += __shfl_xor_sync(0xffffffffu, s, o);
                if (tx == 0 && r < B) atomicAdd(&g_quad[isG * QOFF + r], s);
            }

            __threadfence();
            __syncthreads();
            if (tid == 0) {
                atomicAdd(&g_quadDone, 1u);
                s_item = atomicAdd(&g_ctr, 1u);
            }
            __syncthreads();
            item = s_item;
        }
        else if (item < NITEMS) {
            // ================= streaming copy chunk =================
            unsigned nG = g + 1; if (nG > NG) nG = NG;
            const unsigned chunk = item - nG;

            __syncthreads();
            if (tid == 0) s_item = atomicAdd(&g_ctr, 1u);   // prefetch next

            float4 v[16];
            if (chunk < TCHUNK) {
                // pure text chunk: no bounds, no select
                const size_t base = (size_t)chunk * CHUNK4 + tid;
                #pragma unroll
                for (int j = 0; j < 16; j++)
                    v[j] = __ldcs(&tin[base + (size_t)j * NTHREADS]);
                #pragma unroll
                for (int j = 0; j < 16; j++)
                    __stcs(&dall[base + (size_t)j * NTHREADS], v[j]);
            } else if ((size_t)chunk * CHUNK4 >= t4 &&
                       (size_t)(chunk + 1) * CHUNK4 <= tot4) {
                // pure user chunk, full
                const size_t base = (size_t)chunk * CHUNK4 + tid;
                const size_t ub = base - t4;
                #pragma unroll
                for (int j = 0; j < 16; j++)
                    v[j] = __ldcs(&uin[ub + (size_t)j * NTHREADS]);
                #pragma unroll
                for (int j = 0; j < 16; j++)
                    __stcs(&dall[base + (size_t)j * NTHREADS], v[j]);
            } else {
                // straddle / partial chunk: fully guarded
                const size_t base = (size_t)chunk * CHUNK4 + tid;
                #pragma unroll
                for (int j = 0; j < 16; j++) {
                    const size_t idx = base + (size_t)j * NTHREADS;
                    if (idx < tot4)
                        v[j] = (idx < t4) ? __ldcs(&tin[idx]) : __ldcs(&uin[idx - t4]);
                }
                #pragma unroll
                for (int j = 0; j < 16; j++) {
                    const size_t idx = base + (size_t)j * NTHREADS;
                    if (idx < tot4) __stcs(&dall[idx], v[j]);
                }
            }

            __threadfence();
            __syncthreads();
            if (tid == 0) atomicAdd(&g_copyDone, 1u);
            item = s_item;
        }
        else {
            // ================= finalize rows =================
            const unsigned fitem = item - NITEMS;

            if (tid == 0) {
                while (*(volatile unsigned*)&g_quadDone < NG)     __nanosleep(200);
                while (*(volatile unsigned*)&g_copyDone < NCHUNK) __nanosleep(200);
            }
            __syncthreads();
            __threadfence();

            const int r = (int)fitem * 8 + warp;
            if (r < B) {
                long long u = load_idx(uidx, r, is64);
                const float4* __restrict__ x4  = (const float4*)(text + (size_t)r * SC);
                const float4* __restrict__ g4  = (const float4*)(user + (size_t)u * CDIM);
                const float4* __restrict__ bt4 = (const float4*)bt;
                const float4* __restrict__ bg4 = (const float4*)bg;

                float4 xs[6], gs[6];
                float pxb = 0.f, pgb = 0.f, pxg = 0.f;
                #pragma unroll
                for (int k = 0; k < 6; k++) {
                    xs[k] = x4[lane + 32 * k];
                    gs[k] = g4[lane + 32 * k];
                    const float4 bv = bt4[lane + 32 * k];
                    const float4 gv = bg4[lane + 32 * k];
                    pxb += xs[k].x * bv.x + xs[k].y * bv.y + xs[k].z * bv.z + xs[k].w * bv.w;
                    pgb += gs[k].x * gv.x + gs[k].y * gv.y + gs[k].z * gv.z + gs[k].w * gv.w;
                    pxg += xs[k].x * gs[k].x + xs[k].y * gs[k].y + xs[k].z * gs[k].z + xs[k].w * gs[k].w;
                }
                #pragma unroll
                for (int o = 16; o; o >>= 1) {
                    pxb += __shfl_xor_sync(0xffffffffu, pxb, o);
                    pgb += __shfl_xor_sync(0xffffffffu, pgb, o);
                    pxg += __shfl_xor_sync(0xffffffffu, pxg, o);
                }
                float wa, wc;
                if (lane == 0) {
                    const float a  = g_quad[r] + pxb;          // text_ini . text_tmp
                    const float cq = g_quad[QOFF + r] + pgb;   // graph_tmp . graph_ini
                    const float bq = pxg;                      // graph_ini . text_ini
                    wa = 1.f / (1.f + expf(bq - a));
                    wc = 1.f / (1.f + expf(bq - cq));
                }
                wa = __shfl_sync(0xffffffffu, wa, 0);
                wc = __shfl_sync(0xffffffffu, wc, 0);
                const float wb = 1.f - wa, wd = 1.f - wc;

                float4* __restrict__ oT = (float4*)(outAll + (size_t)r * SC);
                float4* __restrict__ oU = (float4*)(outAll + text_n + (size_t)u * CDIM);
                #pragma unroll
                for (int k = 0; k < 6; k++) {
                    float4 to, uo;
                    to.x = wa * xs[k].x + wb * gs[k].x;  uo.x = wc * gs[k].x + wd * xs[k].x;
                    to.y = wa * xs[k].y + wb * gs[k].y;  uo.y = wc * gs[k].y + wd * xs[k].y;
                    to.z = wa * xs[k].z + wb * gs[k].z;  uo.z = wc * gs[k].z + wd * xs[k].z;
                    to.w = wa * xs[k].w + wb * gs[k].w;  uo.w = wc * gs[k].w + wd * xs[k].w;
                    oT[lane + 32 * k] = to;
                    oU[lane + 32 * k] = uo;
                }
            }

            __syncthreads();
            if (tid == 0) s_item = atomicAdd(&g_ctr, 1u);
            __syncthreads();
            item = s_item;
        }
    }

    // ================= exit: last block resets state for next replay ======
    __syncthreads();
    if (tid == 0) {
        const unsigned t = atomicAdd(&g_exit, 1u);
        s_item = (t == gridDim.x - 1) ? 1u : 0u;
    }
    __syncthreads();
    if (s_item) {
        for (int i = tid; i < 2 * QOFF; i += NTHREADS) g_quad[i] = 0.f;
        __syncthreads();
        if (tid == 0) {
            __threadfence();
            g_quadDone = 0u; g_copyDone = 0u; g_ctr = 0u;
            __threadfence();
            g_exit = 0u;
        }
    }
}

// ---------------------------------------------------------------------------
extern "C" void kernel_launch(void* const* d_in, const int* in_sizes, int n_in,
                              void* d_out, int out_size)
{
    const float* text = (const float*)d_in[0];
    const float* user = (const float*)d_in[1];
    const void*  uidx = d_in[2];
    const float* Wt   = (const float*)d_in[3];
    const float* bt   = (const float*)d_in[4];
    const float* Wg   = (const float*)d_in[5];
    const float* bg   = (const float*)d_in[6];

    const long long text_n = in_sizes[0];
    const long long user_n = in_sizes[1];
    const int B = in_sizes[2];
    const long long SC = text_n / (long long)B;   // S*C
    const long long user_rows = user_n / CDIM;

    const unsigned perM = (unsigned)((B / TM) * JTILES);   // 96
    const unsigned NG = 2 * perM;                           // 192
    const size_t t4   = (size_t)text_n >> 2;
    const size_t tot4 = (size_t)(text_n + user_n) >> 2;
    const unsigned NCHUNK = (unsigned)((tot4 + CHUNK4 - 1) / CHUNK4);
    const unsigned TCHUNK = (unsigned)(t4 / CHUNK4);        // pure-text chunks
    const unsigned NITEMS = NG + NCHUNK;
    unsigned P = (NITEMS / 2) / NG;                         // spread over 1st half
    if (P < 1) P = 1;
    const unsigned NFIN = (unsigned)((B + 7) / 8);
    const unsigned TOTAL = NITEMS + NFIN;

    mega<<<NBLOCKS, NTHREADS>>>(text, user, uidx, Wt, bt, Wg, bg,
                                (float*)d_out,
                                B, SC, text_n, user_n, user_rows,
                                NG, P, NITEMS, NCHUNK, TCHUNK, TOTAL);
}

// round 6
// speedup vs baseline: 2.5513x; 1.0719x over previous
#include <cuda_runtime.h>

#define CDIM  768
#define CDIM4 192           // CDIM/4
#define NTHREADS 256
#define NBLOCKS  304        // 152 SMs * 2 blocks
#define TM 128
#define TN 128
#define TK 32
#define KTILES (CDIM / TK)  // 24
#define JTILES (CDIM / TN)  // 6
#define QOFF 4096           // scratch stride (max B = 4096)
#define CHUNK4 4096         // float4 per copy chunk (64 KB)
#define TMP (TM + 4)        // padded smem row

// quadratic-form scratch: [0,B) text, [QOFF,QOFF+B) graph. MUST be zero at
// kernel entry: zero-initialized at load; re-zeroed by last-exiting block.
__device__ float g_quad[2 * QOFF];
__device__ float g_wc[QOFF];      // per-row graph blend weight (for fixup)
__device__ unsigned g_ctr;        // work-queue head
__device__ unsigned g_passed;     // blocks that finished all pre-finalize work
__device__ unsigned g_exit;       // exited blocks

// user_index may be int64 (declared) or int32 (JAX x64-off default).
__device__ __forceinline__ int detect_is64(const void* uptr, int B, long long nrows) {
    if (B < 2) return 1;
    long long v = ((const long long*)uptr)[B / 2 - 1];
    return (v >= 0 && v < nrows) ? 1 : 0;
}
__device__ __forceinline__ long long load_idx(const void* uptr, int i, int is64) {
    if (is64) return ((const long long*)uptr)[i];
    return (long long)((const int*)uptr)[i];
}

// ---- packed fp32x2 helpers (SASS FFMA2; ptxas never auto-fuses) ----
__device__ __forceinline__ unsigned long long dup2(float a) {
    unsigned long long d; unsigned ai = __float_as_uint(a);
    asm("mov.b64 %0, {%1, %1};" : "=l"(d) : "r"(ai));
    return d;
}
__device__ __forceinline__ void fma2(unsigned long long& acc,
                                     unsigned long long a, unsigned long long b) {
    asm("fma.rn.f32x2 %0, %1, %2, %0;" : "+l"(acc) : "l"(a), "l"(b));
}
__device__ __forceinline__ float2 unpack2(unsigned long long v) {
    float2 r;
    asm("mov.b64 {%0, %1}, %2;" : "=f"(r.x), "=f"(r.y) : "l"(v));
    return r;
}

// ---------------------------------------------------------------------------
// Mega kernel (SM branch). Work items:
//   [0, NITEMS): mixed — i%P==0 && i/P<NG -> GEMM tile; else text copy chunk
//   [NITEMS, TOTAL): finalize text rows (wait g_passed == gridDim.x first).
// Each block signals g_passed ONCE (fence+atomic) when it first grabs an
// item >= NITEMS; finalize waits for all blocks => all copies+GEMM visible.
// The user tensor is copied concurrently by the copy engine (other stream);
// mega does NOT touch outU — it stores wc per row for the fixup kernel.
// ---------------------------------------------------------------------------
__global__ void __launch_bounds__(NTHREADS, 2)
mega(const float* __restrict__ text,
     const float* __restrict__ user,
     const void*  __restrict__ uidx,
     const float* __restrict__ Wt,
     const float* __restrict__ bt,
     const float* __restrict__ Wg,
     const float* __restrict__ bg,
     float* __restrict__ outAll,           // outT (text_n) then outU (user_n)
     int B, long long SC,
     long long text_n, long long user_rows,
     unsigned NG, unsigned P, unsigned NITEMS, unsigned TOTAL)
{
    __shared__ float As[TK][TMP];
    __shared__ float Bs[TK][TMP];
    __shared__ unsigned s_item;

    const int tid  = threadIdx.x;
    const int warp = tid >> 5;
    const int lane = tid & 31;
    const int tx   = tid & 15;    // j-fragment index
    const int ty   = tid >> 4;    // row-fragment index

    const float4* __restrict__ tin = (const float4*)text;
    float4* __restrict__ dall = (float4*)outAll;

    const unsigned perM = NG >> 1;

    if (tid == 0) s_item = atomicAdd(&g_ctr, 1u);
    __syncthreads();
    unsigned item = s_item;
    bool passed = false;

    const int is64 = detect_is64(uidx, B, user_rows);

    for (;;) {
        // once per block: signal that all its copy/GEMM stores are visible
        if (!passed && item >= NITEMS) {
            __threadfence();
            __syncthreads();
            if (tid == 0) atomicAdd(&g_passed, 1u);
            passed = true;
        }
        if (item >= TOTAL) break;

        unsigned g = item / P;
        bool isGemm = (item < NITEMS) && (item - g * P == 0u) && (g < NG);

        if (isGemm) {
            // ================= GEMM bilinear-form tile =================
            const int isG = (g >= perM) ? 1 : 0;
            const int qq  = isG ? (int)(g - perM) : (int)g;
            const int mt  = qq / JTILES;
            const int jt  = qq % JTILES;
            const int row0 = mt * TM;
            const int j0   = jt * TN;
            const float* __restrict__ Wm = isG ? Wg : Wt;

            unsigned long long acc[8][4];
            #pragma unroll
            for (int i = 0; i < 8; i++)
                #pragma unroll
                for (int j = 0; j < 4; j++) acc[i][j] = 0ull;

            for (int kt = 0; kt < KTILES; kt++) {
                const int kb4 = kt * (TK / 4);
                __syncthreads();
                #pragma unroll
                for (int it = 0; it < 4; it++) {
                    const int f  = it * NTHREADS + tid;
                    const int r  = f >> 3;
                    const int qd = f & 7;
                    int rr = row0 + r; if (rr >= B) rr = B - 1;
                    const float* arow;
                    if (isG) {
                        long long u = load_idx(uidx, rr, is64);
                        arow = user + (size_t)u * CDIM;
                    } else {
                        arow = text + (size_t)rr * SC;
                    }
                    const float4 va = __ldg(&((const float4*)arow)[kb4 + qd]);
                    const float4 vb = __ldg(&((const float4*)(Wm + (size_t)(j0 + r) * CDIM))[kb4 + qd]);
                    const int k0 = qd * 4;
                    As[k0 + 0][r] = va.x; As[k0 + 1][r] = va.y;
                    As[k0 + 2][r] = va.z; As[k0 + 3][r] = va.w;
                    Bs[k0 + 0][r] = vb.x; Bs[k0 + 1][r] = vb.y;
                    Bs[k0 + 2][r] = vb.z; Bs[k0 + 3][r] = vb.w;
                }
                __syncthreads();

                #pragma unroll 8
                for (int k = 0; k < TK; k++) {
                    const float4 a0 = *(const float4*)&As[k][ty * 8];
                    const float4 a1 = *(const float4*)&As[k][ty * 8 + 4];
                    const float4 b0 = *(const float4*)&Bs[k][tx * 8];
                    const float4 b1 = *(const float4*)&Bs[k][tx * 8 + 4];
                    unsigned long long bp[4];
                    {
                        float2 t0 = make_float2(b0.x, b0.y), t1 = make_float2(b0.z, b0.w);
                        float2 t2 = make_float2(b1.x, b1.y), t3 = make_float2(b1.z, b1.w);
                        bp[0] = *(unsigned long long*)&t0; bp[1] = *(unsigned long long*)&t1;
                        bp[2] = *(unsigned long long*)&t2; bp[3] = *(unsigned long long*)&t3;
                    }
                    const float av[8] = {a0.x, a0.y, a0.z, a0.w, a1.x, a1.y, a1.z, a1.w};
                    #pragma unroll
                    for (int ii = 0; ii < 8; ii++) {
                        const unsigned long long ad = dup2(av[ii]);
                        #pragma unroll
                        for (int jp = 0; jp < 4; jp++) fma2(acc[ii][jp], ad, bp[jp]);
                    }
                }
            }

            // epilogue: s_r += sum_j P[r,j]*x[r,j]; reduce over tx; atomicAdd
            #pragma unroll
            for (int ii = 0; ii < 8; ii++) {
                const int r = row0 + ty * 8 + ii;
                const int rr = (r < B) ? r : (B - 1);
                const float* xrow;
                if (isG) {
                    long long u = load_idx(uidx, rr, is64);
                    xrow = user + (size_t)u * CDIM;
                } else {
                    xrow = text + (size_t)rr * SC;
                }
                const float4 xa = __ldg(&((const float4*)xrow)[(j0 >> 2) + tx * 2]);
                const float4 xb = __ldg(&((const float4*)xrow)[(j0 >> 2) + tx * 2 + 1]);
                const float2 p0 = unpack2(acc[ii][0]);
                const float2 p1 = unpack2(acc[ii][1]);
                const float2 p2 = unpack2(acc[ii][2]);
                const float2 p3 = unpack2(acc[ii][3]);
                float s = p0.x * xa.x + p0.y * xa.y + p1.x * xa.z + p1.y * xa.w
                        + p2.x * xb.x + p2.y * xb.y + p3.x * xb.z + p3.y * xb.w;
                #pragma unroll
                for (int o = 8; o; o >>= 1) s += __shfl_xor_sync(0xffffffffu, s, o);
                if (tx == 0 && r < B) atomicAdd(&g_quad[isG * QOFF + r], s);
            }

            __syncthreads();
            if (tid == 0) s_item = atomicAdd(&g_ctr, 1u);
            __syncthreads();
            item = s_item;
        }
        else if (item < NITEMS) {
            // ============ streaming text copy chunk (unguarded) ============
            unsigned nG = g + 1; if (nG > NG) nG = NG;
            const unsigned chunk = item - nG;

            __syncthreads();
            if (tid == 0) s_item = atomicAdd(&g_ctr, 1u);   // prefetch next

            const size_t base = (size_t)chunk * CHUNK4 + tid;
            float4 v[16];
            #pragma unroll
            for (int j = 0; j < 16; j++)
                v[j] = __ldcs(&tin[base + (size_t)j * NTHREADS]);
            #pragma unroll
            for (int j = 0; j < 16; j++)
                __stcs(&dall[base + (size_t)j * NTHREADS], v[j]);

            __syncthreads();
            item = s_item;
        }
        else {
            // ================= finalize text rows =================
            const unsigned fitem = item - NITEMS;

            if (tid == 0) {
                while (*(volatile unsigned*)&g_passed < (unsigned)gridDim.x)
                    __nanosleep(100);
            }
            __syncthreads();
            __threadfence();

            const int r = (int)fitem * 8 + warp;
            if (r < B) {
                long long u = load_idx(uidx, r, is64);
                const float4* __restrict__ x4  = (const float4*)(text + (size_t)r * SC);
                const float4* __restrict__ g4  = (const float4*)(user + (size_t)u * CDIM);
                const float4* __restrict__ bt4 = (const float4*)bt;
                const float4* __restrict__ bg4 = (const float4*)bg;

                float4 xs[6], gs[6];
                float pxb = 0.f, pgb = 0.f, pxg = 0.f;
                #pragma unroll
                for (int k = 0; k < 6; k++) {
                    xs[k] = x4[lane + 32 * k];
                    gs[k] = g4[lane + 32 * k];
                    const float4 bv = bt4[lane + 32 * k];
                    const float4 gv = bg4[lane + 32 * k];
                    pxb += xs[k].x * bv.x + xs[k].y * bv.y + xs[k].z * bv.z + xs[k].w * bv.w;
                    pgb += gs[k].x * gv.x + gs[k].y * gv.y + gs[k].z * gv.z + gs[k].w * gv.w;
                    pxg += xs[k].x * gs[k].x + xs[k].y * gs[k].y + xs[k].z * gs[k].z + xs[k].w * gs[k].w;
                }
                #pragma unroll
                for (int o = 16; o; o >>= 1) {
                    pxb += __shfl_xor_sync(0xffffffffu, pxb, o);
                    pgb += __shfl_xor_sync(0xffffffffu, pgb, o);
                    pxg += __shfl_xor_sync(0xffffffffu, pxg, o);
                }
                float wa, wc;
                if (lane == 0) {
                    const float a  = g_quad[r] + pxb;          // text_ini . text_tmp
                    const float cq = g_quad[QOFF + r] + pgb;   // graph_tmp . graph_ini
                    const float bq = pxg;                      // graph_ini . text_ini
                    wa = 1.f / (1.f + expf(bq - a));
                    wc = 1.f / (1.f + expf(bq - cq));
                    g_wc[r] = wc;                              // for fixup kernel
                }
                wa = __shfl_sync(0xffffffffu, wa, 0);
                const float wb = 1.f - wa;

                float4* __restrict__ oT = (float4*)(outAll + (size_t)r * SC);
                #pragma unroll
                for (int k = 0; k < 6; k++) {
                    float4 to;
                    to.x = wa * xs[k].x + wb * gs[k].x;
                    to.y = wa * xs[k].y + wb * gs[k].y;
                    to.z = wa * xs[k].z + wb * gs[k].z;
                    to.w = wa * xs[k].w + wb * gs[k].w;
                    oT[lane + 32 * k] = to;
                }
            }

            __syncthreads();
            if (tid == 0) s_item = atomicAdd(&g_ctr, 1u);
            __syncthreads();
            item = s_item;
        }
    }

    // ================= exit: last block resets state for next replay ======
    __syncthreads();
    if (tid == 0) {
        const unsigned t = atomicAdd(&g_exit, 1u);
        s_item = (t == gridDim.x - 1) ? 1u : 0u;
    }
    __syncthreads();
    if (s_item) {
        for (int i = tid; i < 2 * QOFF; i += NTHREADS) g_quad[i] = 0.f;
        __syncthreads();
        if (tid == 0) {
            __threadfence();
            g_ctr = 0u; g_passed = 0u;
            __threadfence();
            g_exit = 0u;
        }
    }
}

// ---------------------------------------------------------------------------
// Fixup (after join with CE memcpy of user->outU): write blended graph rows.
// ---------------------------------------------------------------------------
__global__ void __launch_bounds__(192)
fixup(const float* __restrict__ text,
      const float* __restrict__ user,
      const void*  __restrict__ uidx,
      float* __restrict__ outAll,
      int B, long long SC, long long text_n, long long user_rows)
{
    const int r = blockIdx.x;
    const int is64 = detect_is64(uidx, B, user_rows);
    const long long u = load_idx(uidx, r, is64);
    const float wc = g_wc[r];
    const float wd = 1.f - wc;

    const float4* __restrict__ xi = (const float4*)(text + (size_t)r * SC);
    const float4* __restrict__ gi = (const float4*)(user + (size_t)u * CDIM);
    float4* __restrict__ o = (float4*)(outAll + text_n + (size_t)u * CDIM);

    const int t = threadIdx.x;
    if (t < CDIM4) {
        const float4 xv = xi[t];
        const float4 gv = gi[t];
        float4 uo;
        uo.x = wc * gv.x + wd * xv.x;
        uo.y = wc * gv.y + wd * xv.y;
        uo.z = wc * gv.z + wd * xv.z;
        uo.w = wc * gv.w + wd * xv.w;
        o[t] = uo;
    }
}

// ---------------------------------------------------------------------------
extern "C" void kernel_launch(void* const* d_in, const int* in_sizes, int n_in,
                              void* d_out, int out_size)
{
    static cudaStream_t s2 = 0;
    static cudaEvent_t evA = 0, evB = 0;
    static bool inited = false;
    if (!inited) {
        cudaStreamCreateWithFlags(&s2, cudaStreamNonBlocking);
        cudaEventCreateWithFlags(&evA, cudaEventDisableTiming);
        cudaEventCreateWithFlags(&evB, cudaEventDisableTiming);
        inited = true;
    }

    const float* text = (const float*)d_in[0];
    const float* user = (const float*)d_in[1];
    const void*  uidx = d_in[2];
    const float* Wt   = (const float*)d_in[3];
    const float* bt   = (const float*)d_in[4];
    const float* Wg   = (const float*)d_in[5];
    const float* bg   = (const float*)d_in[6];

    const long long text_n = in_sizes[0];
    const long long user_n = in_sizes[1];
    const int B = in_sizes[2];
    const long long SC = text_n / (long long)B;   // S*C
    const long long user_rows = user_n / CDIM;

    float* outAll = (float*)d_out;

    const unsigned perM = (unsigned)((B / TM) * JTILES);   // 96
    const unsigned NG = 2 * perM;                           // 192
    const size_t t4 = (size_t)text_n >> 2;
    const unsigned NCHUNK = (unsigned)((t4 + CHUNK4 - 1) / CHUNK4);
    const unsigned NITEMS = NG + NCHUNK;
    unsigned P = (NITEMS / 2) / NG;                         // spread over 1st half
    if (P < 1) P = 1;
    const unsigned NFIN = (unsigned)((B + 7) / 8);
    const unsigned TOTAL = NITEMS + NFIN;

    // fork: copy engine handles user -> outU concurrently with mega
    cudaEventRecord(evA, 0);
    cudaStreamWaitEvent(s2, evA, 0);
    cudaMemcpyAsync(outAll + text_n, user, (size_t)user_n * sizeof(float),
                    cudaMemcpyDeviceToDevice, s2);
    cudaEventRecord(evB, s2);

    mega<<<NBLOCKS, NTHREADS>>>(text, user, uidx, Wt, bt, Wg, bg,
                                outAll, B, SC, text_n, user_rows,
                                NG, P, NITEMS, TOTAL);

    // join, then overwrite the B indexed user rows
    cudaStreamWaitEvent(0, evB, 0);
    fixup<<<B, 192>>>(text, user, uidx, outAll, B, SC, text_n, user_rows);
}